// round 5
// baseline (speedup 1.0000x reference)
#include <cuda_runtime.h>
#include <cuda_bf16.h>

#define NT 256

// X=Y=4, D=6, F_IN=2, F_OUT=10, CX=CY=2, B=1024
// inputs: (1024,4,4,2)  peps: (4,4,2,6,6,6,6)  peps_center: (2,10,6,6,6,6)
// out: (1024,10) float32

struct SmemLayout {
    float Sa[7776];      // ping
    float Sb[7776];      // pong
    float node[1296];    // current node tensor
    float envtop[1296];  // also reused for W at the end
    float envbot[1296];
    float red[8];
    float dots[20];
};

// ---------------- block reduction (sum) ----------------
__device__ __forceinline__ float block_reduce(float v, float* red) {
    #pragma unroll
    for (int o = 16; o; o >>= 1) v += __shfl_xor_sync(0xffffffffu, v, o);
    int w = threadIdx.x >> 5;
    if ((threadIdx.x & 31) == 0) red[w] = v;
    __syncthreads();
    float r;
    if (threadIdx.x < 32) {
        r = (threadIdx.x < 8) ? red[threadIdx.x] : 0.f;
        #pragma unroll
        for (int o = 4; o; o >>= 1) r += __shfl_xor_sync(0xffffffffu, r, o);
        if (threadIdx.x == 0) red[0] = r;
    }
    __syncthreads();
    r = red[0];
    __syncthreads();
    return r;
}

__device__ __forceinline__ void normalize_buf(float* buf, int n, float* red) {
    float ss = 0.f;
    for (int i = threadIdx.x; i < n; i += NT) { float v = buf[i]; ss += v * v; }
    ss = block_reduce(ss, red);
    float inv = rsqrtf(ss);
    for (int i = threadIdx.x; i < n; i += NT) buf[i] *= inv;
    __syncthreads();
}

// ---------------- node construction + normalization ----------------
// buf[u][r][d][l] packed by actual dims (Un,Rn,Dn,Ln); sliced axes keep index 0.
__device__ void make_node(float* buf, const float* __restrict__ peps,
                          const float* __restrict__ inp, int b, int i, int j,
                          int Un, int Rn, int Dn, int Ln, float* red) {
    float x0 = inp[((b * 4 + i) * 4 + j) * 2 + 0];
    float x1 = inp[((b * 4 + i) * 4 + j) * 2 + 1];
    const float* T0 = peps + (size_t)((i * 4 + j) * 2) * 1296;
    const float* T1 = T0 + 1296;
    int n = Un * Rn * Dn * Ln;
    float ss = 0.f;
    for (int idx = threadIdx.x; idx < n; idx += NT) {
        int l = idx % Ln;
        int t = idx / Ln;
        int d = t % Dn;  t /= Dn;
        int r = t % Rn;
        int u = t / Rn;
        int g = ((u * 6 + r) * 6 + d) * 6 + l;
        float v = fmaf(x0, __ldg(T0 + g), x1 * __ldg(T1 + g));
        buf[idx] = v;
        ss += v * v;
    }
    ss = block_reduce(ss, red);
    float inv = rsqrtf(ss);
    for (int idx = threadIdx.x; idx < n; idx += NT) buf[idx] *= inv;
    __syncthreads();
}

// ---------------- generic contraction step ----------------
// out[(m*A+a)*R + r] = sum_{u<U,x<X} Sin[(u*M+m)*X + x] * T[u*su + a*sa + r*sr + x]
__device__ void cstep(const float* __restrict__ Sin, float* __restrict__ Sout,
                      const float* __restrict__ T,
                      int M, int X, int A, int R, int U,
                      int su, int sa, int sr) {
    int total = M * A * R;
    for (int idx = threadIdx.x; idx < total; idx += NT) {
        int r = idx % R;
        int a = (idx / R) % A;
        int m = idx / (A * R);
        float acc = 0.f;
        for (int u = 0; u < U; ++u) {
            const float* sp = Sin + (u * M + m) * X;
            const float* tp = T + u * su + a * sa + r * sr;
            #pragma unroll 6
            for (int x = 0; x < X; ++x) acc = fmaf(sp[x], tp[x], acc);
        }
        Sout[idx] = acc;
    }
    __syncthreads();
}

// ---------------- hot tiled step: M=216, U=X=A=R=6, su=216, sa=6, sr=36 ----------
// out[(m*6+a)*6+r] = sum_{u,x} Sin[u*1296 + m*6 + x] * T[u*216 + r*36 + a*6 + x]
__device__ void cstep_full(const float* __restrict__ Sin, float* __restrict__ Sout,
                           const float* __restrict__ T) {
    int t = threadIdx.x;
    if (t < 216) {
        int mg = t / 6;   // 36 groups of 6 m
        int a  = t % 6;   // node d index
        float acc[36];
        #pragma unroll
        for (int k = 0; k < 36; ++k) acc[k] = 0.f;
        #pragma unroll
        for (int u = 0; u < 6; ++u) {
            float sv[36];
            const float4* sp4 = reinterpret_cast<const float4*>(Sin + u * 1296 + mg * 36);
            #pragma unroll
            for (int q = 0; q < 9; ++q) reinterpret_cast<float4*>(sv)[q] = sp4[q];
            const float* tb = T + u * 216 + a * 6;
            #pragma unroll
            for (int r = 0; r < 6; ++r) {
                float tv[6];
                const float2* tp2 = reinterpret_cast<const float2*>(tb + r * 36);
                #pragma unroll
                for (int q = 0; q < 3; ++q) reinterpret_cast<float2*>(tv)[q] = tp2[q];
                #pragma unroll
                for (int mi = 0; mi < 6; ++mi) {
                    #pragma unroll
                    for (int x = 0; x < 6; ++x)
                        acc[mi * 6 + r] = fmaf(sv[mi * 6 + x], tv[x], acc[mi * 6 + r]);
                }
            }
        }
        #pragma unroll
        for (int mi = 0; mi < 6; ++mi)
            #pragma unroll
            for (int r = 0; r < 6; ++r)
                Sout[((mg * 6 + mi) * 6 + a) * 6 + r] = acc[mi * 6 + r];
    }
    __syncthreads();
}

__global__ void __launch_bounds__(NT, 2)
peps_kernel(const float* __restrict__ inp, const float* __restrict__ peps,
            const float* __restrict__ pc, float* __restrict__ out) {
    extern __shared__ __align__(16) char smem_raw[];
    SmemLayout& S = *reinterpret_cast<SmemLayout*>(smem_raw);
    const int b = blockIdx.x;

    // ================= Row 0 (top) =================
    make_node(S.node, peps, inp, b, 0, 0, 1, 6, 6, 1, S.red);
    // env[d*6+r] = node00[r*6+d]
    if (threadIdx.x < 36) {
        int d = threadIdx.x / 6, r = threadIdx.x % 6;
        S.Sa[d * 6 + r] = S.node[r * 6 + d];
    }
    __syncthreads();
    make_node(S.node, peps, inp, b, 0, 1, 1, 6, 6, 6, S.red);
    cstep(S.Sa, S.Sb, S.node, 6, 6, 6, 6, 1, 0, 6, 36);        // -> 216
    make_node(S.node, peps, inp, b, 0, 2, 1, 6, 6, 6, S.red);
    cstep(S.Sb, S.Sa, S.node, 36, 6, 6, 6, 1, 0, 6, 36);       // -> 1296
    make_node(S.node, peps, inp, b, 0, 3, 1, 1, 6, 6, S.red);
    cstep(S.Sa, S.Sb, S.node, 216, 6, 6, 1, 1, 0, 6, 0);       // -> 1296
    normalize_buf(S.Sb, 1296, S.red);                          // row-0 env in Sb

    // ================= Row 1 =================
    make_node(S.node, peps, inp, b, 1, 0, 6, 6, 6, 1, S.red);
    cstep(S.Sb, S.Sa, S.node, 216, 1, 6, 6, 6, 36, 1, 6);      // -> 7776
    make_node(S.node, peps, inp, b, 1, 1, 6, 6, 6, 6, S.red);
    cstep_full(S.Sa, S.Sb, S.node);                            // -> 7776
    make_node(S.node, peps, inp, b, 1, 2, 6, 6, 6, 6, S.red);
    cstep_full(S.Sb, S.Sa, S.node);                            // -> 7776
    make_node(S.node, peps, inp, b, 1, 3, 6, 1, 6, 6, S.red);
    cstep(S.Sa, S.envtop, S.node, 216, 6, 6, 1, 6, 36, 6, 0);  // -> 1296
    normalize_buf(S.envtop, 1296, S.red);                      // env_top

    // ================= Row 3 (bottom) =================
    make_node(S.node, peps, inp, b, 3, 0, 6, 6, 1, 1, S.red);
    for (int i = threadIdx.x; i < 36; i += NT) S.Sa[i] = S.node[i]; // env (u0, r)
    __syncthreads();
    make_node(S.node, peps, inp, b, 3, 1, 6, 6, 1, 6, S.red);
    cstep(S.Sa, S.Sb, S.node, 6, 6, 6, 6, 1, 0, 36, 6);        // -> 216
    make_node(S.node, peps, inp, b, 3, 2, 6, 6, 1, 6, S.red);
    cstep(S.Sb, S.Sa, S.node, 36, 6, 6, 6, 1, 0, 36, 6);       // -> 1296
    make_node(S.node, peps, inp, b, 3, 3, 6, 1, 1, 6, S.red);
    cstep(S.Sa, S.envbot, S.node, 216, 6, 6, 1, 1, 0, 6, 0);   // -> 1296
    normalize_buf(S.envbot, 1296, S.red);                      // env_bot

    // ================= Row 2 (center row, j=0..1) =================
    make_node(S.node, peps, inp, b, 2, 0, 6, 6, 6, 1, S.red);
    cstep(S.envtop, S.Sa, S.node, 216, 1, 6, 6, 6, 36, 1, 6);  // -> 7776
    make_node(S.node, peps, inp, b, 2, 1, 6, 6, 6, 6, S.red);
    cstep_full(S.Sa, S.Sb, S.node);                            // S1 in Sb: [u2][u3][d0][d1][l2]

    // ================= node(2,3) then E =================
    make_node(S.node, peps, inp, b, 2, 3, 6, 1, 6, 6, S.red);  // [u3][d3][r2]
    // E[k*36 + d2*6 + r2] = sum_d3 envbot[d0,d1,d2,d3] * node23[u3,d3,r2]
    // k = u3*36 + d0*6 + d1. E -> Sa.
    for (int idx = threadIdx.x; idx < 7776; idx += NT) {
        int r2 = idx % 6;
        int d2 = (idx / 6) % 6;
        int k  = idx / 36;
        int u3 = k / 36;
        int d0 = (k / 6) % 6;
        int d1 = k % 6;
        const float* eb  = S.envbot + d0 * 216 + d1 * 36 + d2 * 6;
        const float* n23 = S.node + u3 * 36 + r2;
        float acc = 0.f;
        #pragma unroll
        for (int d3 = 0; d3 < 6; ++d3) acc = fmaf(eb[d3], n23[d3 * 6], acc);
        S.Sa[idx] = acc;
    }
    __syncthreads();

    // ================= W step =================
    // W[u*216 + r*36 + d*6 + l] = sum_k S1[u*1296 + k*6 + l] * E[k*36 + d*6 + r]
    // W -> envtop (reuse).
    {
        int t = threadIdx.x;
        if (t < 216) {
            int i = t / 6;       // u*6 + l
            int d = t % 6;
            int u = i / 6, l = i % 6;
            float acc[6] = {0.f, 0.f, 0.f, 0.f, 0.f, 0.f};
            const float* s1 = S.Sb + u * 1296 + l;   // stride 6 over k
            const float* eb = S.Sa + d * 6;          // + k*36 + r
            for (int k = 0; k < 216; ++k) {
                float s = s1[k * 6];
                const float2* ep = reinterpret_cast<const float2*>(eb + k * 36);
                float ev[6];
                #pragma unroll
                for (int q = 0; q < 3; ++q) reinterpret_cast<float2*>(ev)[q] = ep[q];
                #pragma unroll
                for (int r = 0; r < 6; ++r) acc[r] = fmaf(s, ev[r], acc[r]);
            }
            #pragma unroll
            for (int r = 0; r < 6; ++r)
                S.envtop[u * 216 + r * 36 + d * 6 + l] = acc[r];
        }
        __syncthreads();
    }

    // ================= final: out[o] = sum_p x_p * <Tc[p,o,:], W> =================
    // Center normalization is an o-independent positive scalar -> cancels under
    // the final row normalization, so we use peps_center raw.
    {
        int w = threadIdx.x >> 5, lane = threadIdx.x & 31;
        for (int po = w; po < 20; po += 8) {
            const float* tc = pc + (size_t)po * 1296;
            float s = 0.f;
            for (int g = lane; g < 1296; g += 32) s = fmaf(__ldg(tc + g), S.envtop[g], s);
            #pragma unroll
            for (int o = 16; o; o >>= 1) s += __shfl_xor_sync(0xffffffffu, s, o);
            if (lane == 0) S.dots[po] = s;
        }
        __syncthreads();
        if (threadIdx.x == 0) {
            float x0 = inp[((b * 4 + 2) * 4 + 2) * 2 + 0];
            float x1 = inp[((b * 4 + 2) * 4 + 2) * 2 + 1];
            float raw[10]; float ss = 0.f;
            #pragma unroll
            for (int o = 0; o < 10; ++o) {
                raw[o] = fmaf(x0, S.dots[o], x1 * S.dots[10 + o]);
                ss += raw[o] * raw[o];
            }
            float inv = rsqrtf(ss);
            #pragma unroll
            for (int o = 0; o < 10; ++o) out[b * 10 + o] = raw[o] * inv;
        }
    }
}

extern "C" void kernel_launch(void* const* d_in, const int* in_sizes, int n_in,
                              void* d_out, int out_size) {
    const float *inp = nullptr, *peps = nullptr, *pc = nullptr;
    for (int i = 0; i < n_in; ++i) {
        if (in_sizes[i] == 1024 * 4 * 4 * 2) inp  = (const float*)d_in[i];
        else if (in_sizes[i] == 4 * 4 * 2 * 1296) peps = (const float*)d_in[i];
        else if (in_sizes[i] == 2 * 10 * 1296)    pc   = (const float*)d_in[i];
    }
    int smem = (int)sizeof(SmemLayout);
    cudaFuncSetAttribute(peps_kernel, cudaFuncAttributeMaxDynamicSharedMemorySize, smem);
    peps_kernel<<<1024, NT, smem>>>(inp, peps, pc, (float*)d_out);
}

// round 9
// speedup vs baseline: 1.1621x; 1.1621x over previous
#include <cuda_runtime.h>
#include <cuda_bf16.h>

#define NT 256

// X=Y=4, D=6, F_IN=2, F_OUT=10, CX=CY=2, B=1024
// inputs: (1024,4,4,2)  peps: (4,4,2,6,6,6,6)  peps_center: (2,10,6,6,6,6)
// out: (1024,10) float32
//
// All _unit() normalizations are positive per-batch scalars on tensors feeding
// a multilinear network -> they cancel under the final row-normalization.
// BUT fp32 range requires keeping magnitudes near 1: we keep 3 normalizations
// (row0 env, env_top, env_bot) purely as range-keepers, and max-scale the
// final 10-vector before squaring.

// ---- node arena offsets (floats) ----
#define N00 0       // 36   (r,d)
#define N01 36      // 216  (r,d,l)
#define N02 252     // 216
#define N03 468     // 36   (d,l)
#define N10 504     // 216  (u,r,d)
#define N11 720     // 1296 (u,r,d,l)
#define N12 2016    // 1296
#define N13 3312    // 216  (u,d,l)
#define N30 3528    // 36   (u,r)
#define N31 3564    // 216  (u,r,l)
#define N32 3780    // 216
#define N33 3996    // 36   (u,l)
#define N20 4032    // 216  (u,r,d)
#define N21 4248    // 1296
#define N23 5544    // 216  (u,d,l)
#define NODES_TOTAL 5760

struct Smem {
    float Sa[7776];
    float Sb[7776];
    float nodes[NODES_TOTAL];
    float envtop[1296];
    float envbot[1296];
    float red[8];
    float dots[20];
};

// ---------------- block reduction (sum) ----------------
__device__ __forceinline__ float block_reduce(float v, float* red) {
    #pragma unroll
    for (int o = 16; o; o >>= 1) v += __shfl_xor_sync(0xffffffffu, v, o);
    int w = threadIdx.x >> 5;
    if ((threadIdx.x & 31) == 0) red[w] = v;
    __syncthreads();
    float r;
    if (threadIdx.x < 32) {
        r = (threadIdx.x < 8) ? red[threadIdx.x] : 0.f;
        #pragma unroll
        for (int o = 4; o; o >>= 1) r += __shfl_xor_sync(0xffffffffu, r, o);
        if (threadIdx.x == 0) red[0] = r;
    }
    __syncthreads();
    r = red[0];
    __syncthreads();
    return r;
}

__device__ __forceinline__ void normalize_buf(float* buf, int n, float* red) {
    float ss = 0.f;
    for (int i = threadIdx.x; i < n; i += NT) { float v = buf[i]; ss += v * v; }
    ss = block_reduce(ss, red);
    float inv = rsqrtf(ss);
    for (int i = threadIdx.x; i < n; i += NT) buf[i] *= inv;
    __syncthreads();
}

// ---------------- node fill (no normalization) ----------------
template <int I, int J, int U, int R, int Dd, int L>
__device__ __forceinline__ void fill_node(float* __restrict__ buf,
                                          const float* __restrict__ peps,
                                          const float* __restrict__ xs) {
    const float x0 = xs[(I * 4 + J) * 2 + 0];
    const float x1 = xs[(I * 4 + J) * 2 + 1];
    const float* T0 = peps + (size_t)((I * 4 + J) * 2) * 1296;
    const float* T1 = T0 + 1296;
    constexpr int n = U * R * Dd * L;
    if (n == 1296) {
        const float4* a = reinterpret_cast<const float4*>(T0);
        const float4* c = reinterpret_cast<const float4*>(T1);
        float4* o = reinterpret_cast<float4*>(buf);
        for (int k = threadIdx.x; k < 324; k += NT) {
            float4 va = __ldg(a + k), vb = __ldg(c + k);
            o[k] = make_float4(fmaf(x0, va.x, x1 * vb.x), fmaf(x0, va.y, x1 * vb.y),
                               fmaf(x0, va.z, x1 * vb.z), fmaf(x0, va.w, x1 * vb.w));
        }
    } else {
        for (int idx = threadIdx.x; idx < n; idx += NT) {
            int l = idx % L;
            int t = idx / L;
            int d = t % Dd; t /= Dd;
            int r = t % R;
            int u = t / R;
            int g = ((u * 6 + r) * 6 + d) * 6 + l;
            buf[idx] = fmaf(x0, __ldg(T0 + g), x1 * __ldg(T1 + g));
        }
    }
}

// ---------------- templated contraction step ----------------
// out[(m*A+a)*R + r] = sum_{u<U,x<X} Sin[(u*M+m)*X + x] * T[u*SU + a*SA + r*SR + x]
template <int M, int X, int A, int R, int U, int SU, int SA, int SR>
__device__ __forceinline__ void cstepT(const float* __restrict__ Sin,
                                       float* __restrict__ Sout,
                                       const float* __restrict__ T) {
    constexpr int TOT = M * A * R;
    for (int idx = threadIdx.x; idx < TOT; idx += NT) {
        const int r = idx % R;
        const int a = (idx / R) % A;
        const int m = idx / (A * R);
        float acc = 0.f;
        #pragma unroll
        for (int u = 0; u < U; ++u) {
            if (X == 6) {
                float sv[6], tv[6];
                const float2* sp = reinterpret_cast<const float2*>(Sin + (u * M + m) * 6);
                const float2* tp = reinterpret_cast<const float2*>(T + u * SU + a * SA + r * SR);
                #pragma unroll
                for (int q = 0; q < 3; ++q) {
                    reinterpret_cast<float2*>(sv)[q] = sp[q];
                    reinterpret_cast<float2*>(tv)[q] = tp[q];
                }
                #pragma unroll
                for (int x = 0; x < 6; ++x) acc = fmaf(sv[x], tv[x], acc);
            } else {
                acc = fmaf(Sin[(u * M + m) * X], T[u * SU + a * SA + r * SR], acc);
            }
        }
        Sout[idx] = acc;
    }
    __syncthreads();
}

// ---------------- hot tiled step: M=216, U=X=A=R=6 ----------------
// out[(m*6+a)*6+r] = sum_{u,x} Sin[u*1296 + m*6 + x] * T[u*216 + r*36 + a*6 + x]
__device__ __forceinline__ void cstep_full(const float* __restrict__ Sin,
                                           float* __restrict__ Sout,
                                           const float* __restrict__ T) {
    const int t = threadIdx.x;
    if (t < 216) {
        const int mg = t / 6;
        const int a  = t % 6;
        float acc[36];
        #pragma unroll
        for (int k = 0; k < 36; ++k) acc[k] = 0.f;
        #pragma unroll
        for (int u = 0; u < 6; ++u) {
            float sv[36];
            const float4* sp4 = reinterpret_cast<const float4*>(Sin + u * 1296 + mg * 36);
            #pragma unroll
            for (int q = 0; q < 9; ++q) reinterpret_cast<float4*>(sv)[q] = sp4[q];
            const float* tb = T + u * 216 + a * 6;
            #pragma unroll
            for (int r = 0; r < 6; ++r) {
                float tv[6];
                const float2* tp2 = reinterpret_cast<const float2*>(tb + r * 36);
                #pragma unroll
                for (int q = 0; q < 3; ++q) reinterpret_cast<float2*>(tv)[q] = tp2[q];
                #pragma unroll
                for (int mi = 0; mi < 6; ++mi) {
                    #pragma unroll
                    for (int x = 0; x < 6; ++x)
                        acc[mi * 6 + r] = fmaf(sv[mi * 6 + x], tv[x], acc[mi * 6 + r]);
                }
            }
        }
        #pragma unroll
        for (int mi = 0; mi < 6; ++mi)
            #pragma unroll
            for (int r = 0; r < 6; ++r)
                Sout[((mg * 6 + mi) * 6 + a) * 6 + r] = acc[mi * 6 + r];
    }
    __syncthreads();
}

__global__ void __launch_bounds__(NT, 2)
peps_kernel(const float* __restrict__ inp, const float* __restrict__ peps,
            const float* __restrict__ pc, float* __restrict__ out) {
    extern __shared__ __align__(16) char smem_raw[];
    Smem& S = *reinterpret_cast<Smem*>(smem_raw);
    const int b = blockIdx.x;
    const float* xs = inp + b * 32;  // (4,4,2)
    float* nd = S.nodes;

    // ============ Phase 1: build all 15 node tensors (one barrier) ============
    fill_node<0, 0, 1, 6, 6, 1>(nd + N00, peps, xs);
    fill_node<0, 1, 1, 6, 6, 6>(nd + N01, peps, xs);
    fill_node<0, 2, 1, 6, 6, 6>(nd + N02, peps, xs);
    fill_node<0, 3, 1, 1, 6, 6>(nd + N03, peps, xs);
    fill_node<1, 0, 6, 6, 6, 1>(nd + N10, peps, xs);
    fill_node<1, 1, 6, 6, 6, 6>(nd + N11, peps, xs);
    fill_node<1, 2, 6, 6, 6, 6>(nd + N12, peps, xs);
    fill_node<1, 3, 6, 1, 6, 6>(nd + N13, peps, xs);
    fill_node<3, 0, 6, 6, 1, 1>(nd + N30, peps, xs);
    fill_node<3, 1, 6, 6, 1, 6>(nd + N31, peps, xs);
    fill_node<3, 2, 6, 6, 1, 6>(nd + N32, peps, xs);
    fill_node<3, 3, 6, 1, 1, 6>(nd + N33, peps, xs);
    fill_node<2, 0, 6, 6, 6, 1>(nd + N20, peps, xs);
    fill_node<2, 1, 6, 6, 6, 6>(nd + N21, peps, xs);
    fill_node<2, 3, 6, 1, 6, 6>(nd + N23, peps, xs);
    __syncthreads();

    // ============ Row 0 (top boundary) ============
    if (threadIdx.x < 36) {
        int d = threadIdx.x / 6, r = threadIdx.x % 6;
        S.Sa[d * 6 + r] = nd[N00 + r * 6 + d];  // transpose (r,d)->(d,r)
    }
    __syncthreads();
    cstepT<6,   6, 6, 6, 1, 0, 6, 36>(S.Sa, S.Sb, nd + N01);  // -> 216
    cstepT<36,  6, 6, 6, 1, 0, 6, 36>(S.Sb, S.Sa, nd + N02);  // -> 1296
    cstepT<216, 6, 6, 1, 1, 0, 6, 0 >(S.Sa, S.Sb, nd + N03);  // -> 1296
    normalize_buf(S.Sb, 1296, S.red);                         // range-keeper

    // ============ Row 1 ============
    cstepT<216, 1, 6, 6, 6, 36, 1, 6>(S.Sb, S.Sa, nd + N10);  // -> 7776
    cstep_full(S.Sa, S.Sb, nd + N11);                          // -> 7776
    cstep_full(S.Sb, S.Sa, nd + N12);                          // -> 7776
    cstepT<216, 6, 6, 1, 6, 36, 6, 0>(S.Sa, S.envtop, nd + N13);  // env_top 1296
    normalize_buf(S.envtop, 1296, S.red);                     // range-keeper

    // ============ Row 3 (bottom boundary) ============
    for (int i = threadIdx.x; i < 36; i += NT) S.Sa[i] = nd[N30 + i];  // (u,r)
    __syncthreads();
    cstepT<6,   6, 6, 6, 1, 0, 36, 6>(S.Sa, S.Sb, nd + N31);  // -> 216
    cstepT<36,  6, 6, 6, 1, 0, 36, 6>(S.Sb, S.Sa, nd + N32);  // -> 1296
    cstepT<216, 6, 6, 1, 1, 0, 6, 0 >(S.Sa, S.envbot, nd + N33);  // env_bot 1296
    normalize_buf(S.envbot, 1296, S.red);                     // range-keeper

    // ============ Row 2 (center row, j=0,1) ============
    cstepT<216, 1, 6, 6, 6, 36, 1, 6>(S.envtop, S.Sa, nd + N20);  // -> 7776
    cstep_full(S.Sa, S.Sb, nd + N21);                              // S1 in Sb

    // ============ E step: fold env_bot with node(2,3) ============
    // E[k*36 + d2*6 + r2] = sum_d3 envbot[d0,d1,d2,d3] * n23[u3,d3,r2]
    // k = u3*36 + d0*6 + d1.  E -> Sa.
    for (int idx = threadIdx.x; idx < 7776; idx += NT) {
        const int r2 = idx % 6;
        const int d2 = (idx / 6) % 6;
        const int k  = idx / 36;
        const int u3 = k / 36;
        const int d0 = (k / 6) % 6;
        const int d1 = k % 6;
        const float* eb  = S.envbot + d0 * 216 + d1 * 36 + d2 * 6;
        const float* n23 = nd + N23 + u3 * 36 + r2;
        float acc = 0.f;
        #pragma unroll
        for (int d3 = 0; d3 < 6; ++d3) acc = fmaf(eb[d3], n23[d3 * 6], acc);
        S.Sa[idx] = acc;
    }
    __syncthreads();

    // ============ W step ============
    // W[u*216 + r*36 + d*6 + l] = sum_k S1[u*1296 + k*6 + l] * E[k*36 + d*6 + r]
    {
        const int t = threadIdx.x;
        if (t < 216) {
            const int i = t / 6;  // u*6 + l
            const int d = t % 6;
            const int u = i / 6, l = i % 6;
            float acc[6] = {0.f, 0.f, 0.f, 0.f, 0.f, 0.f};
            const float* s1 = S.Sb + u * 1296 + l;
            const float* eb = S.Sa + d * 6;
            for (int k = 0; k < 216; ++k) {
                const float s = s1[k * 6];
                float ev[6];
                const float2* ep = reinterpret_cast<const float2*>(eb + k * 36);
                #pragma unroll
                for (int q = 0; q < 3; ++q) reinterpret_cast<float2*>(ev)[q] = ep[q];
                #pragma unroll
                for (int r = 0; r < 6; ++r) acc[r] = fmaf(s, ev[r], acc[r]);
            }
            #pragma unroll
            for (int r = 0; r < 6; ++r)
                S.envtop[u * 216 + r * 36 + d * 6 + l] = acc[r];
        }
        __syncthreads();
    }

    // ============ final: out[o] ∝ sum_p x_p * <Tc[p,o,:], W> ============
    {
        const int w = threadIdx.x >> 5, lane = threadIdx.x & 31;
        for (int po = w; po < 20; po += 8) {
            const float* tc = pc + (size_t)po * 1296;
            float s = 0.f;
            for (int g = lane; g < 1296; g += 32) s = fmaf(__ldg(tc + g), S.envtop[g], s);
            #pragma unroll
            for (int o = 16; o; o >>= 1) s += __shfl_xor_sync(0xffffffffu, s, o);
            if (lane == 0) S.dots[po] = s;
        }
        __syncthreads();
        if (threadIdx.x == 0) {
            const float x0 = xs[(2 * 4 + 2) * 2 + 0];
            const float x1 = xs[(2 * 4 + 2) * 2 + 1];
            float raw[10];
            float m = 0.f;
            #pragma unroll
            for (int o = 0; o < 10; ++o) {
                raw[o] = fmaf(x0, S.dots[o], x1 * S.dots[10 + o]);
                m = fmaxf(m, fabsf(raw[o]));
            }
            // max-scale before squaring: immune to underflow/overflow of ss
            const float im = 1.0f / m;
            float ss = 0.f;
            #pragma unroll
            for (int o = 0; o < 10; ++o) {
                const float v = raw[o] * im;
                ss += v * v;
            }
            const float inv = rsqrtf(ss) * im;
            #pragma unroll
            for (int o = 0; o < 10; ++o) out[b * 10 + o] = raw[o] * inv;
        }
    }
}

extern "C" void kernel_launch(void* const* d_in, const int* in_sizes, int n_in,
                              void* d_out, int out_size) {
    const float *inp = nullptr, *peps = nullptr, *pc = nullptr;
    for (int i = 0; i < n_in; ++i) {
        if (in_sizes[i] == 1024 * 4 * 4 * 2)      inp  = (const float*)d_in[i];
        else if (in_sizes[i] == 4 * 4 * 2 * 1296) peps = (const float*)d_in[i];
        else if (in_sizes[i] == 2 * 10 * 1296)    pc   = (const float*)d_in[i];
    }
    const int smem = (int)sizeof(Smem);
    cudaFuncSetAttribute(peps_kernel, cudaFuncAttributeMaxDynamicSharedMemorySize, smem);
    peps_kernel<<<1024, NT, smem>>>(inp, peps, pc, (float*)d_out);
}

// round 10
// speedup vs baseline: 1.9190x; 1.6513x over previous
#include <cuda_runtime.h>
#include <cuda_bf16.h>

#define NT 256
typedef unsigned long long u64;

// X=Y=4, D=6, F_IN=2, F_OUT=10, CX=CY=2, B=1024
// inputs: (1024,4,4,2)  peps: (4,4,2,6,6,6,6)  peps_center: (2,10,6,6,6,6)
// out: (1024,10) float32
//
// All _unit() normalizations are positive per-batch scalars feeding a
// multilinear network -> they cancel under the final row-normalization.
// Keep 3 (row0 env, env_top, env_bot) purely as fp32 range-keepers, plus
// max-scaling of the final 10-vector.

// ---------------- f32x2 packed-math helpers (FFMA2 path) ----------------
static __device__ __forceinline__ u64 pk2(float a, float b) {
    u64 r; asm("mov.b64 %0,{%1,%2};" : "=l"(r) : "f"(a), "f"(b)); return r;
}
static __device__ __forceinline__ void fma2(u64& d, u64 a, u64 b) {
    asm("fma.rn.f32x2 %0,%1,%2,%0;" : "+l"(d) : "l"(a), "l"(b));
}

// ---- node arena offsets (floats) ----
#define N00 0       // 36   (r,d)
#define N01 36      // 216  (r,d,l)
#define N02 252     // 216
#define N03 468     // 36   (d,l)
#define N10 504     // 216  (u,r,d)
#define N11 720     // 1296 TT layout [u][d][l][r]
#define N12 2016    // 1296 TT
#define N13 3312    // 216  (u,d,l)
#define N30 3528    // 36   (u,r)
#define N31 3564    // 216  (u,r,l)
#define N32 3780    // 216
#define N33 3996    // 36   (u,l)
#define N20 4032    // 216  (u,r,d)
#define N21 4248    // 1296 TT
#define N23 5544    // 216  (u,d,l)
#define NODES_TOTAL 5760

struct Smem {
    float Sa[7776];
    float Sb[7776];
    float nodes[NODES_TOTAL];
    float envtop[1296];
    float envbot[1296];
    float red[8];
    float dots[20];
};

// ---------------- block reduction (sum) ----------------
__device__ __forceinline__ float block_reduce(float v, float* red) {
    #pragma unroll
    for (int o = 16; o; o >>= 1) v += __shfl_xor_sync(0xffffffffu, v, o);
    int w = threadIdx.x >> 5;
    if ((threadIdx.x & 31) == 0) red[w] = v;
    __syncthreads();
    float r;
    if (threadIdx.x < 32) {
        r = (threadIdx.x < 8) ? red[threadIdx.x] : 0.f;
        #pragma unroll
        for (int o = 4; o; o >>= 1) r += __shfl_xor_sync(0xffffffffu, r, o);
        if (threadIdx.x == 0) red[0] = r;
    }
    __syncthreads();
    r = red[0];
    __syncthreads();
    return r;
}

__device__ __forceinline__ void normalize1296(float* buf, float* red) {
    float4* b4 = reinterpret_cast<float4*>(buf);
    float ss = 0.f;
    for (int i = threadIdx.x; i < 324; i += NT) {
        float4 v = b4[i];
        ss += v.x * v.x + v.y * v.y + v.z * v.z + v.w * v.w;
    }
    ss = block_reduce(ss, red);
    float inv = rsqrtf(ss);
    for (int i = threadIdx.x; i < 324; i += NT) {
        float4 v = b4[i];
        b4[i] = make_float4(v.x * inv, v.y * inv, v.z * inv, v.w * inv);
    }
    __syncthreads();
}

// ---------------- node fills ----------------
template <int I, int J, int U, int R, int Dd, int L>
__device__ __forceinline__ void fill_node(float* __restrict__ buf,
                                          const float* __restrict__ peps,
                                          const float* __restrict__ xs) {
    const float x0 = xs[(I * 4 + J) * 2 + 0];
    const float x1 = xs[(I * 4 + J) * 2 + 1];
    const float* T0 = peps + (size_t)((I * 4 + J) * 2) * 1296;
    const float* T1 = T0 + 1296;
    constexpr int n = U * R * Dd * L;
    for (int idx = threadIdx.x; idx < n; idx += NT) {
        int l = idx % L;
        int t = idx / L;
        int d = t % Dd; t /= Dd;
        int r = t % R;
        int u = t / R;
        int g = ((u * 6 + r) * 6 + d) * 6 + l;
        buf[idx] = fmaf(x0, __ldg(T0 + g), x1 * __ldg(T1 + g));
    }
}

// full node in transposed layout TT[u*216 + d*36 + l*6 + r] = Node[u][r][d][l]
template <int I, int J>
__device__ __forceinline__ void fill_node_tt(float* __restrict__ buf,
                                             const float* __restrict__ peps,
                                             const float* __restrict__ xs) {
    const float x0 = xs[(I * 4 + J) * 2 + 0];
    const float x1 = xs[(I * 4 + J) * 2 + 1];
    const float* T0 = peps + (size_t)((I * 4 + J) * 2) * 1296;
    const float* T1 = T0 + 1296;
    for (int g = threadIdx.x; g < 1296; g += NT) {   // g linear: coalesced LDG
        int l = g % 6, d = (g / 6) % 6, r = (g / 36) % 6, u = g / 216;
        buf[u * 216 + d * 36 + l * 6 + r] = fmaf(x0, __ldg(T0 + g), x1 * __ldg(T1 + g));
    }
}

// ---------------- specialized contraction steps (no div/mod in loops) ------

// M=6, U=1: out[t] = sum_x Sin[m*6+x] * T[a*SA + r*SR + x], t=m*36+a*6+r
template <int SA, int SR>
__device__ __forceinline__ void step6(const float* __restrict__ Sin,
                                      float* __restrict__ Sout,
                                      const float* __restrict__ T) {
    const int t = threadIdx.x;
    if (t < 216) {
        const int m = t / 36, a = (t / 6) % 6, r = t % 6;
        const float* sp = Sin + m * 6;
        const float* tp = T + a * SA + r * SR;
        float acc = 0.f;
        #pragma unroll
        for (int x = 0; x < 6; ++x) acc = fmaf(sp[x], tp[x], acc);
        Sout[t] = acc;
    }
    __syncthreads();
}

// M=36, U=1: thread=(m,a) computes 6 r. out base = t*6.
template <int SA, int SR>
__device__ __forceinline__ void step36(const float* __restrict__ Sin,
                                       float* __restrict__ Sout,
                                       const float* __restrict__ T) {
    const int t = threadIdx.x;
    if (t < 216) {
        const int m = t / 6, a = t % 6;
        float sv[6];
        const float2* sp = reinterpret_cast<const float2*>(Sin + m * 6);
        #pragma unroll
        for (int q = 0; q < 3; ++q) { float2 v = sp[q]; sv[q*2] = v.x; sv[q*2+1] = v.y; }
        float acc[6];
        #pragma unroll
        for (int r = 0; r < 6; ++r) {
            const float2* tp = reinterpret_cast<const float2*>(T + a * SA + r * SR);
            float tv[6];
            #pragma unroll
            for (int q = 0; q < 3; ++q) { float2 v = tp[q]; tv[q*2] = v.x; tv[q*2+1] = v.y; }
            float s = 0.f;
            #pragma unroll
            for (int x = 0; x < 6; ++x) s = fmaf(sv[x], tv[x], s);
            acc[r] = s;
        }
        float2* op = reinterpret_cast<float2*>(Sout + t * 6);
        #pragma unroll
        for (int q = 0; q < 3; ++q) op[q] = make_float2(acc[q*2], acc[q*2+1]);
    }
    __syncthreads();
}

// M=216, X=6, R=1, U=1: out[m*6+a] = sum_x Sin[m*6+x]*T[a*6+x]
__device__ __forceinline__ void stepX6R1(const float* __restrict__ Sin,
                                         float* __restrict__ Sout,
                                         const float* __restrict__ T) {
    const int m = threadIdx.x;
    if (m < 216) {
        float sv[6];
        const float2* sp = reinterpret_cast<const float2*>(Sin + m * 6);
        #pragma unroll
        for (int q = 0; q < 3; ++q) { float2 v = sp[q]; sv[q*2] = v.x; sv[q*2+1] = v.y; }
        float tt[36];
        const float4* p = reinterpret_cast<const float4*>(T);
        #pragma unroll
        for (int q = 0; q < 9; ++q) { float4 v = p[q]; tt[q*4]=v.x; tt[q*4+1]=v.y; tt[q*4+2]=v.z; tt[q*4+3]=v.w; }
        float acc[6];
        #pragma unroll
        for (int a = 0; a < 6; ++a) {
            float s = 0.f;
            #pragma unroll
            for (int x = 0; x < 6; ++x) s = fmaf(sv[x], tt[a*6+x], s);
            acc[a] = s;
        }
        float2* op = reinterpret_cast<float2*>(Sout + m * 6);
        #pragma unroll
        for (int q = 0; q < 3; ++q) op[q] = make_float2(acc[q*2], acc[q*2+1]);
    }
    __syncthreads();
}

// X=1 "insert new row" (N10/N20): out[m*36+a*6+r] = sum_u Sin[u*216+m]*T[u*36+r*6+a]
__device__ __forceinline__ void insert_step(const float* __restrict__ Sin,
                                            float* __restrict__ Sout,
                                            const float* __restrict__ T) {
    const int m = threadIdx.x;
    if (m < 216) {
        float acc[36];
        #pragma unroll
        for (int i = 0; i < 36; ++i) acc[i] = 0.f;
        #pragma unroll
        for (int u = 0; u < 6; ++u) {
            const float s = Sin[u * 216 + m];
            float tt[36];
            const float4* p = reinterpret_cast<const float4*>(T + u * 36);  // broadcast
            #pragma unroll
            for (int q = 0; q < 9; ++q) { float4 v = p[q]; tt[q*4]=v.x; tt[q*4+1]=v.y; tt[q*4+2]=v.z; tt[q*4+3]=v.w; }
            #pragma unroll
            for (int a = 0; a < 6; ++a)
                #pragma unroll
                for (int r = 0; r < 6; ++r)
                    acc[a * 6 + r] = fmaf(s, tt[r * 6 + a], acc[a * 6 + r]);
        }
        float4* op = reinterpret_cast<float4*>(Sout + m * 36);
        #pragma unroll
        for (int q = 0; q < 9; ++q) op[q] = make_float4(acc[q*4], acc[q*4+1], acc[q*4+2], acc[q*4+3]);
    }
    __syncthreads();
}

// N13-type: out[m*6+a] = sum_{u,x} Sin[(u*216+m)*6+x] * T[u*36+a*6+x]
__device__ __forceinline__ void contract_u_step(const float* __restrict__ Sin,
                                                float* __restrict__ Sout,
                                                const float* __restrict__ T) {
    const int m = threadIdx.x;
    if (m < 216) {
        float acc[6] = {0.f, 0.f, 0.f, 0.f, 0.f, 0.f};
        #pragma unroll
        for (int u = 0; u < 6; ++u) {
            float sv[6];
            const float2* sp = reinterpret_cast<const float2*>(Sin + (u * 216 + m) * 6);
            #pragma unroll
            for (int q = 0; q < 3; ++q) { float2 v = sp[q]; sv[q*2] = v.x; sv[q*2+1] = v.y; }
            float tt[36];
            const float4* p = reinterpret_cast<const float4*>(T + u * 36);  // broadcast
            #pragma unroll
            for (int q = 0; q < 9; ++q) { float4 v = p[q]; tt[q*4]=v.x; tt[q*4+1]=v.y; tt[q*4+2]=v.z; tt[q*4+3]=v.w; }
            #pragma unroll
            for (int a = 0; a < 6; ++a) {
                float s = acc[a];
                #pragma unroll
                for (int x = 0; x < 6; ++x) s = fmaf(sv[x], tt[a*6+x], s);
                acc[a] = s;
            }
        }
        float2* op = reinterpret_cast<float2*>(Sout + m * 6);
        #pragma unroll
        for (int q = 0; q < 3; ++q) op[q] = make_float2(acc[q*2], acc[q*2+1]);
    }
    __syncthreads();
}

// ---------------- hot step with TT node + FFMA2 (r packed) ----------------
// out[mg*216 + mi*36 + a*6 + r] = sum_{u,x} Sin[u*1296+(mg*6+mi)*6+x] * TT[u*216+a*36+x*6+r]
__device__ __forceinline__ void cstep_full_tt(const float* __restrict__ Sin,
                                              float* __restrict__ Sout,
                                              const float* __restrict__ TT) {
    const int t = threadIdx.x;
    if (t < 216) {
        const int mg = t / 6, a = t % 6;
        u64 acc[18];
        #pragma unroll
        for (int i = 0; i < 18; ++i) acc[i] = 0ull;
        #pragma unroll
        for (int u = 0; u < 6; ++u) {
            u64 tt2[18];
            const u64* tp = reinterpret_cast<const u64*>(TT + u * 216 + a * 36);
            #pragma unroll
            for (int q = 0; q < 18; ++q) tt2[q] = tp[q];
            #pragma unroll
            for (int mi = 0; mi < 6; ++mi) {
                float sv[6];
                const float2* sp = reinterpret_cast<const float2*>(Sin + u * 1296 + (mg * 6 + mi) * 6);
                #pragma unroll
                for (int q = 0; q < 3; ++q) { float2 v = sp[q]; sv[q*2] = v.x; sv[q*2+1] = v.y; }
                #pragma unroll
                for (int x = 0; x < 6; ++x) {
                    const u64 s2 = pk2(sv[x], sv[x]);
                    #pragma unroll
                    for (int rp = 0; rp < 3; ++rp) fma2(acc[mi*3+rp], s2, tt2[x*3+rp]);
                }
            }
        }
        float* ob = Sout + mg * 216 + a * 6;
        #pragma unroll
        for (int mi = 0; mi < 6; ++mi) {
            u64* op = reinterpret_cast<u64*>(ob + mi * 36);
            #pragma unroll
            for (int rp = 0; rp < 3; ++rp) op[rp] = acc[mi*3+rp];
        }
    }
    __syncthreads();
}

__global__ void __launch_bounds__(NT, 2)
peps_kernel(const float* __restrict__ inp, const float* __restrict__ peps,
            const float* __restrict__ pc, float* __restrict__ out) {
    extern __shared__ __align__(16) char smem_raw[];
    Smem& S = *reinterpret_cast<Smem*>(smem_raw);
    const int b = blockIdx.x;
    const float* xs = inp + b * 32;
    float* nd = S.nodes;

    // ============ Phase 1: build all 15 node tensors (one barrier) ============
    fill_node<0, 0, 1, 6, 6, 1>(nd + N00, peps, xs);
    fill_node<0, 1, 1, 6, 6, 6>(nd + N01, peps, xs);
    fill_node<0, 2, 1, 6, 6, 6>(nd + N02, peps, xs);
    fill_node<0, 3, 1, 1, 6, 6>(nd + N03, peps, xs);
    fill_node<1, 0, 6, 6, 6, 1>(nd + N10, peps, xs);
    fill_node_tt<1, 1>(nd + N11, peps, xs);
    fill_node_tt<1, 2>(nd + N12, peps, xs);
    fill_node<1, 3, 6, 1, 6, 6>(nd + N13, peps, xs);
    fill_node<3, 0, 6, 6, 1, 1>(nd + N30, peps, xs);
    fill_node<3, 1, 6, 6, 1, 6>(nd + N31, peps, xs);
    fill_node<3, 2, 6, 6, 1, 6>(nd + N32, peps, xs);
    fill_node<3, 3, 6, 1, 1, 6>(nd + N33, peps, xs);
    fill_node<2, 0, 6, 6, 6, 1>(nd + N20, peps, xs);
    fill_node_tt<2, 1>(nd + N21, peps, xs);
    fill_node<2, 3, 6, 1, 6, 6>(nd + N23, peps, xs);
    __syncthreads();

    // ============ Row 0 (top boundary) ============
    if (threadIdx.x < 36) {
        int d = threadIdx.x / 6, r = threadIdx.x % 6;
        S.Sa[d * 6 + r] = nd[N00 + r * 6 + d];
    }
    __syncthreads();
    step6<6, 36>(S.Sa, S.Sb, nd + N01);       // -> 216
    step36<6, 36>(S.Sb, S.Sa, nd + N02);      // -> 1296
    stepX6R1(S.Sa, S.Sb, nd + N03);           // -> 1296
    normalize1296(S.Sb, S.red);               // range-keeper

    // ============ Row 1 ============
    insert_step(S.Sb, S.Sa, nd + N10);        // -> 7776
    cstep_full_tt(S.Sa, S.Sb, nd + N11);      // -> 7776
    cstep_full_tt(S.Sb, S.Sa, nd + N12);      // -> 7776
    contract_u_step(S.Sa, S.envtop, nd + N13);// env_top 1296
    normalize1296(S.envtop, S.red);           // range-keeper

    // ============ Row 3 (bottom boundary) ============
    for (int i = threadIdx.x; i < 36; i += NT) S.Sa[i] = nd[N30 + i];
    __syncthreads();
    step6<36, 6>(S.Sa, S.Sb, nd + N31);       // -> 216
    step36<36, 6>(S.Sb, S.Sa, nd + N32);      // -> 1296
    stepX6R1(S.Sa, S.envbot, nd + N33);       // env_bot 1296
    normalize1296(S.envbot, S.red);           // range-keeper

    // ============ Row 2 (center row, j=0,1) ============
    insert_step(S.envtop, S.Sa, nd + N20);    // -> 7776
    cstep_full_tt(S.Sa, S.Sb, nd + N21);      // S1 in Sb

    // ============ E step: thread-per-k, FFMA2 over r ============
    // E[k*36 + d2*6 + r2] = sum_d3 envbot[d0,d1,d2,d3] * n23[u3,d3,r2], k=u3*36+d0*6+d1
    {
        const int t = threadIdx.x;
        if (t < 216) {
            const int u3 = t / 36, d0 = (t / 6) % 6, d1 = t % 6;
            float eb[36];
            const float4* p = reinterpret_cast<const float4*>(S.envbot + d0 * 216 + d1 * 36);
            #pragma unroll
            for (int q = 0; q < 9; ++q) { float4 v = p[q]; eb[q*4]=v.x; eb[q*4+1]=v.y; eb[q*4+2]=v.z; eb[q*4+3]=v.w; }
            u64 n2[18];
            const u64* np = reinterpret_cast<const u64*>(nd + N23 + u3 * 36);
            #pragma unroll
            for (int q = 0; q < 18; ++q) n2[q] = np[q];
            u64 acc[18];
            #pragma unroll
            for (int i = 0; i < 18; ++i) acc[i] = 0ull;
            #pragma unroll
            for (int d3 = 0; d3 < 6; ++d3)
                #pragma unroll
                for (int d2 = 0; d2 < 6; ++d2) {
                    const u64 e2 = pk2(eb[d2*6+d3], eb[d2*6+d3]);
                    #pragma unroll
                    for (int rp = 0; rp < 3; ++rp) fma2(acc[d2*3+rp], e2, n2[d3*3+rp]);
                }
            u64* op = reinterpret_cast<u64*>(S.Sa + t * 36);
            #pragma unroll
            for (int i = 0; i < 18; ++i) op[i] = acc[i];
        }
        __syncthreads();
    }

    // ============ W step: thread-per-(u,d,r), FFMA2 over l ============
    // W[u*216 + r*36 + d*6 + l] = sum_k S1[u*1296 + k*6 + l] * E[k*36 + d*6 + r]
    {
        const int t = threadIdx.x;
        if (t < 216) {
            const int u = t / 36, d = (t / 6) % 6, r = t % 6;
            u64 acc0 = 0ull, acc1 = 0ull, acc2v = 0ull;
            const u64* sp = reinterpret_cast<const u64*>(S.Sb + u * 1296);
            const float* ep = S.Sa + d * 6 + r;
            #pragma unroll 4
            for (int k = 0; k < 216; ++k) {
                const u64 s0 = sp[k*3], s1 = sp[k*3+1], s2 = sp[k*3+2];
                const float e = ep[k * 36];
                const u64 e2 = pk2(e, e);
                fma2(acc0, s0, e2); fma2(acc1, s1, e2); fma2(acc2v, s2, e2);
            }
            u64* op = reinterpret_cast<u64*>(S.envtop + u * 216 + r * 36 + d * 6);
            op[0] = acc0; op[1] = acc1; op[2] = acc2v;
        }
        __syncthreads();
    }

    // ============ final: out[o] ∝ sum_p x_p * <Tc[p,o,:], W> ============
    {
        const int w = threadIdx.x >> 5, lane = threadIdx.x & 31;
        const float4* wv = reinterpret_cast<const float4*>(S.envtop);
        for (int po = w; po < 20; po += 8) {
            const float4* tc = reinterpret_cast<const float4*>(pc + (size_t)po * 1296);
            float s = 0.f;
            for (int g = lane; g < 324; g += 32) {
                float4 a = __ldg(tc + g), v = wv[g];
                s = fmaf(a.x, v.x, s); s = fmaf(a.y, v.y, s);
                s = fmaf(a.z, v.z, s); s = fmaf(a.w, v.w, s);
            }
            #pragma unroll
            for (int o = 16; o; o >>= 1) s += __shfl_xor_sync(0xffffffffu, s, o);
            if (lane == 0) S.dots[po] = s;
        }
        __syncthreads();
        if (threadIdx.x == 0) {
            const float x0 = xs[(2 * 4 + 2) * 2 + 0];
            const float x1 = xs[(2 * 4 + 2) * 2 + 1];
            float raw[10];
            float m = 0.f;
            #pragma unroll
            for (int o = 0; o < 10; ++o) {
                raw[o] = fmaf(x0, S.dots[o], x1 * S.dots[10 + o]);
                m = fmaxf(m, fabsf(raw[o]));
            }
            const float im = 1.0f / m;
            float ss = 0.f;
            #pragma unroll
            for (int o = 0; o < 10; ++o) { const float v = raw[o] * im; ss += v * v; }
            const float inv = rsqrtf(ss) * im;
            #pragma unroll
            for (int o = 0; o < 10; ++o) out[b * 10 + o] = raw[o] * inv;
        }
    }
}

extern "C" void kernel_launch(void* const* d_in, const int* in_sizes, int n_in,
                              void* d_out, int out_size) {
    const float *inp = nullptr, *peps = nullptr, *pc = nullptr;
    for (int i = 0; i < n_in; ++i) {
        if (in_sizes[i] == 1024 * 4 * 4 * 2)      inp  = (const float*)d_in[i];
        else if (in_sizes[i] == 4 * 4 * 2 * 1296) peps = (const float*)d_in[i];
        else if (in_sizes[i] == 2 * 10 * 1296)    pc   = (const float*)d_in[i];
    }
    const int smem = (int)sizeof(Smem);
    cudaFuncSetAttribute(peps_kernel, cudaFuncAttributeMaxDynamicSharedMemorySize, smem);
    peps_kernel<<<1024, NT, smem>>>(inp, peps, pc, (float*)d_out);
}